// round 16
// baseline (speedup 1.0000x reference)
#include <cuda_runtime.h>
#include <cuda_fp16.h>
#include <cstdint>

#define BB 32
#define SS 512
#define DD 768

static const long N_SD = (long)BB * SS * DD;   // 12,582,912

// ---------------- scratch (static device globals; no allocations) ----------
__device__ __half g_x1h [BB * SS * DD];   // fp16 hi of x1 (natural [s][d])
__device__ __half g_x1l [BB * SS * DD];
__device__ __half g_x2h [BB * SS * DD];   // fp16 hi of x2 (natural [t][d]; flat view = [e][t] too)
__device__ __half g_x2l [BB * SS * DD];
__device__ __half g_Wch [DD * DD];        // fp16 hi of Wc (natural [d][e])
__device__ __half g_Wcl [DD * DD];
__device__ __half g_x1wh[BB * SS * DD];   // x1w hi/lo (natural [s][e])
__device__ __half g_x1wl[BB * SS * DD];
__device__ __half g_P1  [BB * SS * SS];   // single-plane fp16 P1 [s][t]
__device__ __half g_P2T [BB * SS * SS];   // single-plane fp16 P2^T [t][s]
__device__ float g_A  [BB * SS * SS];     // fp32 logits
__device__ float g_rowmax[BB * SS];
__device__ float g_rowrs [BB * SS];
__device__ float g_bias1 [BB * SS];
__device__ float g_bias2 [BB * SS];
__device__ float g_pcm [BB * 8 * SS];     // per-chunk column max partials
__device__ float g_pcs [BB * 8 * SS];     // per-chunk column sum partials

// ---------------- helpers ----------------------------------------------------
__device__ __forceinline__ uint32_t smem_to_u32(const void* p) {
    uint32_t a;
    asm("{ .reg .u64 t; cvta.to.shared.u64 t, %1; cvt.u32.u64 %0, t; }" : "=r"(a) : "l"(p));
    return a;
}
__device__ __forceinline__ void cp_async16(uint32_t dst, const void* src) {
    asm volatile("cp.async.cg.shared.global [%0], [%1], 16;" :: "r"(dst), "l"(src));
}
__device__ __forceinline__ void ldsm_x4(uint32_t* r, uint32_t addr) {
    asm volatile("ldmatrix.sync.aligned.m8n8.x4.shared.b16 {%0,%1,%2,%3}, [%4];"
                 : "=r"(r[0]), "=r"(r[1]), "=r"(r[2]), "=r"(r[3]) : "r"(addr));
}
__device__ __forceinline__ void ldsm_x4_t(uint32_t* r, uint32_t addr) {
    asm volatile("ldmatrix.sync.aligned.m8n8.x4.trans.shared.b16 {%0,%1,%2,%3}, [%4];"
                 : "=r"(r[0]), "=r"(r[1]), "=r"(r[2]), "=r"(r[3]) : "r"(addr));
}
__device__ __forceinline__ void mma16816(float* d, const uint32_t* a, const uint32_t* b) {
    asm volatile(
        "mma.sync.aligned.m16n8k16.row.col.f32.f16.f16.f32 "
        "{%0,%1,%2,%3}, {%4,%5,%6,%7}, {%8,%9}, {%0,%1,%2,%3};"
        : "+f"(d[0]), "+f"(d[1]), "+f"(d[2]), "+f"(d[3])
        : "r"(a[0]), "r"(a[1]), "r"(a[2]), "r"(a[3]), "r"(b[0]), "r"(b[1]));
}

union Pack4 { __half b[4]; uint2 u; };
__device__ __forceinline__ void split1(float v, __half& h, __half& l) {
    h = __float2half_rn(v);
    l = __float2half_rn(v - __half2float(h));
}

// ---------------- fused convert + bias: one warp per row ---------------------
__global__ void conv_bias(const float* __restrict__ x1, const float* __restrict__ x2,
                          const float* __restrict__ W1, const float* __restrict__ W2)
{
    int gw = blockIdx.x * 8 + (threadIdx.x >> 5);
    int lane = threadIdx.x & 31;
    const int total = BB * SS;
    const float* x; const float* W; __half* oh; __half* ol; float* bout; int row;
    if (gw < total) { x = x1; W = W1; oh = g_x1h; ol = g_x1l; bout = g_bias1; row = gw; }
    else            { x = x2; W = W2; oh = g_x2h; ol = g_x2l; bout = g_bias2; row = gw - total; }

    const float4* xr = (const float4*)(x + (long)row * DD);
    const float4* W4 = (const float4*)W;
    uint2* ohp = (uint2*)(oh + (long)row * DD);
    uint2* olp = (uint2*)(ol + (long)row * DD);

    float s = 0.f;
    #pragma unroll
    for (int i = 0; i < 6; i++) {            // 192 float4 per row / 32 lanes
        int idx = i * 32 + lane;
        float4 a = xr[idx], wv = W4[idx];
        s += a.x * wv.x + a.y * wv.y + a.z * wv.z + a.w * wv.w;
        Pack4 h, l;
        split1(a.x, h.b[0], l.b[0]);
        split1(a.y, h.b[1], l.b[1]);
        split1(a.z, h.b[2], l.b[2]);
        split1(a.w, h.b[3], l.b[3]);
        ohp[idx] = h.u;
        olp[idx] = l.u;
    }
    #pragma unroll
    for (int o = 16; o; o >>= 1) s += __shfl_xor_sync(0xffffffffu, s, o);
    if (lane == 0) bout[row] = s;
}

// ---------------- convert: fp32 -> fp16 hi/lo (elementwise, for Wc) ----------
__global__ void conv_hl(const float4* __restrict__ in,
                        __half* __restrict__ oh, __half* __restrict__ ol)
{
    long i = (long)blockIdx.x * 256 + threadIdx.x;
    float4 v = in[i];
    Pack4 h, l;
    split1(v.x, h.b[0], l.b[0]);
    split1(v.y, h.b[1], l.b[1]);
    split1(v.z, h.b[2], l.b[2]);
    split1(v.w, h.b[3], l.b[3]);
    ((uint2*)oh)[i] = h.u;
    ((uint2*)ol)[i] = l.u;
}

// ---------------- mma.sync split-fp16 GEMM, 64x64 warp tiles -----------------
// Block tile 128x128, 128 threads (4 warps, 2M x 2N), warp tile 64x64, BK=32.
// Pipeline order: wait -> sync -> issue next load -> compute (race-free; load
// of chunk c+1 still overlaps compute of chunk c).
// TERMS=3: C = Ah@Bh + Ah@Bl + Al@Bh   [logits path]
// TERMS=2: C = Ah@Bh + Ah@Bl           [output path, A = P]
// DUAL=1: gridDim.z = 2*BB; z>=BB selects the second operand set (G5+G6 merged).
// EPI 0: fp32 C.  EPI 1: fp16 hi/lo C.  EPI 2: fp32 C + biasR + biasC.
#define TILEA   (128 * 80)   // A plane: 128 rows x 32 fp16, pad to 40 -> 10240 B
#define TILEB2  (32 * 256)   // B plane: 32 k-rows x 128 fp16 = 8192 B (swizzled)

template <int EPI, int TERMS, int DUAL>
__global__ void __launch_bounds__(128, 2) gemm_tc(
    const __half* __restrict__ Ah, const __half* __restrict__ Al, long sA, int lda,
    const __half* __restrict__ Bh, const __half* __restrict__ Bl, long sB, int ldb,
    int K,
    float* __restrict__ C, __half* __restrict__ Ch, __half* __restrict__ Cl,
    long sC, int ldc,
    const float* __restrict__ biasR, const float* __restrict__ biasC, int Mtot, int Ntot,
    const __half* __restrict__ Ah2, const __half* __restrict__ Bh2,
    const __half* __restrict__ Bl2, float* __restrict__ C2)
{
    constexpr int NA = (TERMS == 3) ? 2 : 1;
    constexpr int STAGEB = NA * TILEA + 2 * TILEB2;

    extern __shared__ char smem[];
    const uint32_t sbase = smem_to_u32(smem);
    const int tid = threadIdx.x;
    const int lane = tid & 31;
    const int wm = (tid >> 5) >> 1, wn = (tid >> 5) & 1;   // 2x2 warp grid
    const int bm = blockIdx.y * 128, bn = blockIdx.x * 128;

    int zz = blockIdx.z;
    const int sel = DUAL ? (zz >= BB) : 0;
    const int bz  = DUAL ? (zz & (BB - 1)) : zz;

    const __half* AhS = (DUAL && sel) ? Ah2 : Ah;
    const __half* BhS = (DUAL && sel) ? Bh2 : Bh;
    const __half* BlS = (DUAL && sel) ? Bl2 : Bl;
    float*        CS  = (DUAL && sel) ? C2  : C;

    const __half* aP[2] = { AhS + (long)bz * sA,
                            (TERMS == 3) ? (Al + (long)bz * sA) : nullptr };
    const __half* bP[2] = { BhS + (long)bz * sB, BlS + (long)bz * sB };

    float acc[4][8][4];
    #pragma unroll
    for (int i = 0; i < 4; i++)
        #pragma unroll
        for (int j = 0; j < 8; j++)
            #pragma unroll
            for (int q = 0; q < 4; q++) acc[i][j][q] = 0.f;

    const int NC = K >> 5;

    #define LOAD_STAGE(cc, st) do {                                            \
        uint32_t dst0 = sbase + (st) * STAGEB;                                 \
        int k0 = (cc) << 5;                                                    \
        _Pragma("unroll")                                                      \
        for (int p = 0; p < NA; p++)                                           \
            _Pragma("unroll")                                                  \
            for (int h = 0; h < 4; h++) {                                      \
                int slot = tid + h * 128;                                      \
                int row = slot >> 2, seg = slot & 3;                           \
                cp_async16(dst0 + p * TILEA + row * 80 + seg * 16,             \
                           aP[p] + (long)(bm + row) * lda + k0 + seg * 8);     \
            }                                                                  \
        _Pragma("unroll")                                                      \
        for (int p = 0; p < 2; p++)                                            \
            _Pragma("unroll")                                                  \
            for (int h = 0; h < 4; h++) {                                      \
                int slot = tid + h * 128;                                      \
                int row = slot >> 4, seg = slot & 15;                          \
                uint32_t bo = (uint32_t)(row << 8) + (uint32_t)(seg << 4);     \
                bo ^= (uint32_t)(row & 7) << 4;                                \
                cp_async16(dst0 + NA * TILEA + p * TILEB2 + bo,                \
                           bP[p] + (long)(k0 + row) * ldb + bn + seg * 8);     \
            }                                                                  \
        asm volatile("cp.async.commit_group;");                                \
    } while (0)

    LOAD_STAGE(0, 0);

    const int lr = lane & 15;              // A frag row
    const int lc = (lane >> 4) << 3;       // A frag k-col
    const int g8  = lane >> 3;
    const int rowp = ((g8 & 1) << 3) + (lane & 7);   // 0..15 (k within 16)
    const int cs8  = (g8 >> 1) << 3;                 // 0 or 8 (n within 16)

    for (int c = 0; c < NC; c++) {
        asm volatile("cp.async.wait_group 0;");   // chunk c's data landed
        __syncthreads();                          // all warps done with c-1's buffer
        if (c + 1 < NC) {
            LOAD_STAGE(c + 1, (c + 1) & 1);       // overlaps compute of chunk c
        }

        uint32_t sAh = sbase + (c & 1) * STAGEB;
        uint32_t sAl = sAh + TILEA;                  // valid if TERMS==3
        uint32_t sBh = sAh + NA * TILEA;
        uint32_t sBl = sBh + TILEB2;

        #pragma unroll
        for (int kk = 0; kk < 2; kk++) {
            uint32_t fa_h[4][4], fa_l[4][4];
            #pragma unroll
            for (int mm = 0; mm < 4; mm++) {
                uint32_t off = (uint32_t)(wm * 64 + mm * 16 + lr) * 80
                             + (uint32_t)(kk * 16 + lc) * 2;
                ldsm_x4(fa_h[mm], sAh + off);
                if (TERMS == 3) ldsm_x4(fa_l[mm], sAl + off);
            }
            uint32_t fb_h[4][4], fb_l[4][4];
            #pragma unroll
            for (int nn = 0; nn < 4; nn++) {
                uint32_t koff = (uint32_t)(kk * 16 + rowp);
                uint32_t bo = (koff << 8) + (uint32_t)(wn * 64 + nn * 16 + cs8) * 2;
                bo ^= (koff & 7) << 4;
                ldsm_x4_t(fb_h[nn], sBh + bo);
                ldsm_x4_t(fb_l[nn], sBl + bo);
            }
            // term-major issue: consecutive MMAs hit different accumulators
            #pragma unroll
            for (int mm = 0; mm < 4; mm++) {
                #pragma unroll
                for (int nt = 0; nt < 8; nt++) {
                    const int nn = nt >> 1, n2 = nt & 1;
                    uint32_t bh2[2] = { fb_h[nn][2 * n2], fb_h[nn][2 * n2 + 1] };
                    mma16816(acc[mm][nt], fa_h[mm], bh2);
                }
            }
            #pragma unroll
            for (int mm = 0; mm < 4; mm++) {
                #pragma unroll
                for (int nt = 0; nt < 8; nt++) {
                    const int nn = nt >> 1, n2 = nt & 1;
                    uint32_t bl2[2] = { fb_l[nn][2 * n2], fb_l[nn][2 * n2 + 1] };
                    mma16816(acc[mm][nt], fa_h[mm], bl2);
                }
            }
            if (TERMS == 3) {
                #pragma unroll
                for (int mm = 0; mm < 4; mm++) {
                    #pragma unroll
                    for (int nt = 0; nt < 8; nt++) {
                        const int nn = nt >> 1, n2 = nt & 1;
                        uint32_t bh2[2] = { fb_h[nn][2 * n2], fb_h[nn][2 * n2 + 1] };
                        mma16816(acc[mm][nt], fa_l[mm], bh2);
                    }
                }
            }
        }
        __syncthreads();
    }

    // ---- epilogue (warp covers 64 rows x 64 cols)
    const int er0 = bm + wm * 64 + (lane >> 2);
    const int ec0 = bn + wn * 64 + ((lane & 3) << 1);
    #pragma unroll
    for (int mm = 0; mm < 4; mm++) {
        #pragma unroll
        for (int nt = 0; nt < 8; nt++) {
            int row = er0 + mm * 16;
            int col = ec0 + nt * 8;
            float v0 = acc[mm][nt][0], v1 = acc[mm][nt][1];
            float v2 = acc[mm][nt][2], v3 = acc[mm][nt][3];
            if (EPI == 1) {
                __half h0, l0, h1, l1;
                long o = (long)bz * sC + (long)row * ldc + col;
                split1(v0, h0, l0); split1(v1, h1, l1);
                *(__half2*)(Ch + o) = __half2(h0, h1);
                *(__half2*)(Cl + o) = __half2(l0, l1);
                o += (long)8 * ldc;
                split1(v2, h0, l0); split1(v3, h1, l1);
                *(__half2*)(Ch + o) = __half2(h0, h1);
                *(__half2*)(Cl + o) = __half2(l0, l1);
            } else {
                if (EPI == 2) {
                    float bc0 = biasC[bz * Ntot + col], bc1 = biasC[bz * Ntot + col + 1];
                    float br0 = biasR[bz * Mtot + row], br8 = biasR[bz * Mtot + row + 8];
                    v0 += br0 + bc0; v1 += br0 + bc1;
                    v2 += br8 + bc0; v3 += br8 + bc1;
                }
                long o = (long)bz * sC + (long)row * ldc + col;
                *(float2*)(CS + o) = make_float2(v0, v1);
                *(float2*)(CS + o + (long)8 * ldc) = make_float2(v2, v3);
            }
        }
    }
}

// ---------------- fused softmax stats: one A read ----------------------------
__global__ void __launch_bounds__(256) stats_fused()
{
    int b = blockIdx.y, chunk = blockIdx.x;
    int w = threadIdx.x >> 5, lane = threadIdx.x & 31;
    const float* A = g_A + (long)b * SS * SS;

    float cm[16], cs[16];
    #pragma unroll
    for (int q = 0; q < 16; q++) { cm[q] = -1e30f; cs[q] = 0.f; }

    #pragma unroll
    for (int r8 = 0; r8 < 8; r8++) {
        int s = chunk * 64 + w * 8 + r8;
        const float4* ar = (const float4*)(A + (long)s * SS);
        float v[16];
        #pragma unroll
        for (int it = 0; it < 4; it++) {
            float4 t4 = ar[it * 32 + lane];
            v[it * 4 + 0] = t4.x; v[it * 4 + 1] = t4.y;
            v[it * 4 + 2] = t4.z; v[it * 4 + 3] = t4.w;
        }
        float rm = v[0];
        #pragma unroll
        for (int q = 1; q < 16; q++) rm = fmaxf(rm, v[q]);
        #pragma unroll
        for (int o = 16; o; o >>= 1) rm = fmaxf(rm, __shfl_xor_sync(0xffffffffu, rm, o));
        float rs = 0.f;
        #pragma unroll
        for (int q = 0; q < 16; q++) rs += __expf(v[q] - rm);
        #pragma unroll
        for (int o = 16; o; o >>= 1) rs += __shfl_xor_sync(0xffffffffu, rs, o);
        if (lane == 0) { g_rowmax[b * SS + s] = rm; g_rowrs[b * SS + s] = 1.0f / rs; }
        #pragma unroll
        for (int q = 0; q < 16; q++) {
            float nm = fmaxf(cm[q], v[q]);
            cs[q] = cs[q] * __expf(cm[q] - nm) + __expf(v[q] - nm);
            cm[q] = nm;
        }
    }

    __shared__ float scm[8][SS], scs[8][SS];
    #pragma unroll
    for (int it = 0; it < 4; it++)
        #pragma unroll
        for (int q = 0; q < 4; q++) {
            int col = it * 128 + lane * 4 + q;
            scm[w][col] = cm[it * 4 + q];
            scs[w][col] = cs[it * 4 + q];
        }
    __syncthreads();

    #pragma unroll
    for (int j = 0; j < 2; j++) {
        int col = threadIdx.x + j * 256;
        float M = scm[0][col];
        #pragma unroll
        for (int ww = 1; ww < 8; ww++) M = fmaxf(M, scm[ww][col]);
        float S = 0.f;
        #pragma unroll
        for (int ww = 0; ww < 8; ww++) S += scs[ww][col] * __expf(scm[ww][col] - M);
        g_pcm[((long)b * 8 + chunk) * SS + col] = M;
        g_pcs[((long)b * 8 + chunk) * SS + col] = S;
    }
}

// ---------------- probabilities: P1 (fp16) and P2^T (fp16) -------------------
// Col stats derived inline from the 8 per-chunk partials (stats_combine folded in).
__global__ void prob_kernel()
{
    __shared__ float p2t[64 * 65];
    __shared__ float scm[64], scr[64];
    int b = blockIdx.z;
    int bs0 = blockIdx.y * 64, bt0 = blockIdx.x * 64;
    const float* A = g_A + (long)b * SS * SS;
    int tid = threadIdx.x;

    // combine 8 chunk partials for this block's 64 columns
    if (tid < 64) {
        int t = bt0 + tid;
        float M = -1e30f;
        #pragma unroll
        for (int c = 0; c < 8; c++) M = fmaxf(M, g_pcm[((long)b * 8 + c) * SS + t]);
        float S = 0.f;
        #pragma unroll
        for (int c = 0; c < 8; c++)
            S += g_pcs[((long)b * 8 + c) * SS + t] * __expf(g_pcm[((long)b * 8 + c) * SS + t] - M);
        scm[tid] = M;
        scr[tid] = 1.0f / S;
    }
    __syncthreads();

    #pragma unroll
    for (int it = 0; it < 4; it++) {
        int idx = tid + it * 256;
        int r = idx >> 4, c4 = idx & 15;
        int s = bs0 + r;
        float4 v = *(const float4*)(A + (long)s * SS + bt0 + c4 * 4);
        float rm = g_rowmax[b * SS + s];
        float rr = g_rowrs [b * SS + s];
        const float4 cm = *(const float4*)(scm + c4 * 4);
        const float4 cr = *(const float4*)(scr + c4 * 4);
        Pack4 h;
        h.b[0] = __float2half_rn(__expf(v.x - cm.x) * cr.x);
        h.b[1] = __float2half_rn(__expf(v.y - cm.y) * cr.y);
        h.b[2] = __float2half_rn(__expf(v.z - cm.z) * cr.z);
        h.b[3] = __float2half_rn(__expf(v.w - cm.w) * cr.w);
        long o1 = (long)b * SS * SS + (long)s * SS + bt0 + c4 * 4;
        *(uint2*)(g_P1 + o1) = h.u;
        float p2v[4] = { __expf(v.x - rm) * rr, __expf(v.y - rm) * rr,
                         __expf(v.z - rm) * rr, __expf(v.w - rm) * rr };
        #pragma unroll
        for (int q = 0; q < 4; q++) p2t[(c4 * 4 + q) * 65 + r] = p2v[q];
    }
    __syncthreads();
    int c = tid >> 2, g = tid & 3;
    #pragma unroll
    for (int j = 0; j < 4; j++) {
        int rr0 = g * 16 + j * 4;
        Pack4 h;
        #pragma unroll
        for (int q = 0; q < 4; q++) h.b[q] = __float2half_rn(p2t[c * 65 + rr0 + q]);
        long o = (long)b * SS * SS + (long)(bt0 + c) * SS + bs0 + rr0;
        *(uint2*)(g_P2T + o) = h.u;
    }
}

// ---------------- launch -----------------------------------------------------
extern "C" void kernel_launch(void* const* d_in, const int* in_sizes, int n_in,
                              void* d_out, int out_size)
{
    const float* x1 = (const float*)d_in[0];
    const float* x2 = (const float*)d_in[1];
    const float* Wc = (const float*)d_in[2];
    const float* W1 = (const float*)d_in[3];
    const float* W2 = (const float*)d_in[4];
    float* out1 = (float*)d_out;
    float* out2 = out1 + N_SD;

    __half *x1h, *x1l, *x2h, *x2l, *Wch, *Wcl, *x1wh, *x1wl, *P1, *P2T;
    float *pA, *pb1, *pb2;
    cudaGetSymbolAddress((void**)&x1h,  g_x1h);
    cudaGetSymbolAddress((void**)&x1l,  g_x1l);
    cudaGetSymbolAddress((void**)&x2h,  g_x2h);
    cudaGetSymbolAddress((void**)&x2l,  g_x2l);
    cudaGetSymbolAddress((void**)&Wch,  g_Wch);
    cudaGetSymbolAddress((void**)&Wcl,  g_Wcl);
    cudaGetSymbolAddress((void**)&x1wh, g_x1wh);
    cudaGetSymbolAddress((void**)&x1wl, g_x1wl);
    cudaGetSymbolAddress((void**)&P1,   g_P1);
    cudaGetSymbolAddress((void**)&P2T,  g_P2T);
    cudaGetSymbolAddress((void**)&pA,   g_A);
    cudaGetSymbolAddress((void**)&pb1,  g_bias1);
    cudaGetSymbolAddress((void**)&pb2,  g_bias2);

    const int SMEM_T3 = 2 * (2 * TILEA + 2 * TILEB2);   // 73728
    const int SMEM_T2 = 2 * (1 * TILEA + 2 * TILEB2);   // 53248
    cudaFuncSetAttribute(gemm_tc<1, 3, 0>, cudaFuncAttributeMaxDynamicSharedMemorySize, SMEM_T3);
    cudaFuncSetAttribute(gemm_tc<2, 3, 0>, cudaFuncAttributeMaxDynamicSharedMemorySize, SMEM_T3);
    cudaFuncSetAttribute(gemm_tc<0, 2, 1>, cudaFuncAttributeMaxDynamicSharedMemorySize, SMEM_T2);

    const long sSD = (long)SS * DD;
    const long sSq = (long)SS * SS;

    // fused hi/lo converts + bias dots (one read of x1, x2)
    conv_bias<<<(2 * BB * SS) / 8, 256>>>(x1, x2, W1, W2);
    conv_hl<<<(DD * DD / 4) / 256, 256>>>((const float4*)Wc, Wch, Wcl);

    // G1: x1w = x1 @ Wc  (M=512,N=768,K=768); B = Wc natural [d][e]
    gemm_tc<1, 3, 0><<<dim3(DD / 128, SS / 128, BB), 128, SMEM_T3>>>(
        x1h, x1l, sSD, DD, Wch, Wcl, 0, DD, DD,
        nullptr, x1wh, x1wl, sSD, DD, nullptr, nullptr, SS, DD,
        nullptr, nullptr, nullptr, nullptr);

    // G3: A = x1w @ x2r + biases (M=512,N=512,K=768); B = x2 flat viewed [e][t] (ldb=SS)
    gemm_tc<2, 3, 0><<<dim3(SS / 128, SS / 128, BB), 128, SMEM_T3>>>(
        x1wh, x1wl, sSD, DD, x2h, x2l, sSD, SS, DD,
        pA, nullptr, nullptr, sSq, SS, pb1, pb2, SS, SS,
        nullptr, nullptr, nullptr, nullptr);

    // fused row+col stats (one A read); col partials combined inside prob_kernel
    stats_fused<<<dim3(8, BB), 256>>>();
    prob_kernel<<<dim3(SS / 64, SS / 64, BB), 256>>>();

    // G5+G6 merged: z<32 -> f_x1 = P1 @ x2 ; z>=32 -> f_x2 = P2^T @ x1
    gemm_tc<0, 2, 1><<<dim3(DD / 128, SS / 128, 2 * BB), 128, SMEM_T2>>>(
        P1, nullptr, sSq, SS, x2h, x2l, sSD, DD, SS,
        out1, nullptr, nullptr, sSD, DD, nullptr, nullptr, SS, DD,
        P2T, x1h, x1l, out2);
}

// round 17
// speedup vs baseline: 1.0375x; 1.0375x over previous
#include <cuda_runtime.h>
#include <cuda_fp16.h>
#include <cstdint>

#define BB 32
#define SS 512
#define DD 768

static const long N_SD = (long)BB * SS * DD;   // 12,582,912

// ---------------- scratch (static device globals; no allocations) ----------
__device__ __half g_x1h [BB * SS * DD];   // fp16 hi of x1 (natural [s][d])
__device__ __half g_x1l [BB * SS * DD];
__device__ __half g_x2h [BB * SS * DD];   // fp16 hi of x2 (natural [t][d]; flat view = [e][t] too)
__device__ __half g_x2l [BB * SS * DD];
__device__ __half g_Wch [DD * DD];        // fp16 hi of Wc (natural [d][e])
__device__ __half g_Wcl [DD * DD];
__device__ __half g_x1wh[BB * SS * DD];   // x1w hi/lo (natural [s][e])
__device__ __half g_x1wl[BB * SS * DD];
__device__ __half g_P1  [BB * SS * SS];   // single-plane fp16 P1 [s][t]
__device__ __half g_P2T [BB * SS * SS];   // single-plane fp16 P2^T [t][s]
__device__ float g_A  [BB * SS * SS];     // fp32 logits
__device__ float g_bias1 [BB * SS];
__device__ float g_bias2 [BB * SS];
__device__ float g_prm [BB * 8 * SS];     // per-colchunk row max partials
__device__ float g_prs [BB * 8 * SS];     // per-colchunk row sum partials
__device__ float g_pcm [BB * 8 * SS];     // per-rowchunk col max partials
__device__ float g_pcs [BB * 8 * SS];     // per-rowchunk col sum partials

// ---------------- helpers ----------------------------------------------------
__device__ __forceinline__ uint32_t smem_to_u32(const void* p) {
    uint32_t a;
    asm("{ .reg .u64 t; cvta.to.shared.u64 t, %1; cvt.u32.u64 %0, t; }" : "=r"(a) : "l"(p));
    return a;
}
__device__ __forceinline__ void cp_async16(uint32_t dst, const void* src) {
    asm volatile("cp.async.cg.shared.global [%0], [%1], 16;" :: "r"(dst), "l"(src));
}
__device__ __forceinline__ void ldsm_x4(uint32_t* r, uint32_t addr) {
    asm volatile("ldmatrix.sync.aligned.m8n8.x4.shared.b16 {%0,%1,%2,%3}, [%4];"
                 : "=r"(r[0]), "=r"(r[1]), "=r"(r[2]), "=r"(r[3]) : "r"(addr));
}
__device__ __forceinline__ void ldsm_x4_t(uint32_t* r, uint32_t addr) {
    asm volatile("ldmatrix.sync.aligned.m8n8.x4.trans.shared.b16 {%0,%1,%2,%3}, [%4];"
                 : "=r"(r[0]), "=r"(r[1]), "=r"(r[2]), "=r"(r[3]) : "r"(addr));
}
__device__ __forceinline__ void mma16816(float* d, const uint32_t* a, const uint32_t* b) {
    asm volatile(
        "mma.sync.aligned.m16n8k16.row.col.f32.f16.f16.f32 "
        "{%0,%1,%2,%3}, {%4,%5,%6,%7}, {%8,%9}, {%0,%1,%2,%3};"
        : "+f"(d[0]), "+f"(d[1]), "+f"(d[2]), "+f"(d[3])
        : "r"(a[0]), "r"(a[1]), "r"(a[2]), "r"(a[3]), "r"(b[0]), "r"(b[1]));
}

union Pack4 { __half b[4]; uint2 u; };
__device__ __forceinline__ void split1(float v, __half& h, __half& l) {
    h = __float2half_rn(v);
    l = __float2half_rn(v - __half2float(h));
}

// ---------------- fused convert + bias: one warp per row ---------------------
__global__ void conv_bias(const float* __restrict__ x1, const float* __restrict__ x2,
                          const float* __restrict__ W1, const float* __restrict__ W2)
{
    int gw = blockIdx.x * 8 + (threadIdx.x >> 5);
    int lane = threadIdx.x & 31;
    const int total = BB * SS;
    const float* x; const float* W; __half* oh; __half* ol; float* bout; int row;
    if (gw < total) { x = x1; W = W1; oh = g_x1h; ol = g_x1l; bout = g_bias1; row = gw; }
    else            { x = x2; W = W2; oh = g_x2h; ol = g_x2l; bout = g_bias2; row = gw - total; }

    const float4* xr = (const float4*)(x + (long)row * DD);
    const float4* W4 = (const float4*)W;
    uint2* ohp = (uint2*)(oh + (long)row * DD);
    uint2* olp = (uint2*)(ol + (long)row * DD);

    float s = 0.f;
    #pragma unroll
    for (int i = 0; i < 6; i++) {            // 192 float4 per row / 32 lanes
        int idx = i * 32 + lane;
        float4 a = xr[idx], wv = W4[idx];
        s += a.x * wv.x + a.y * wv.y + a.z * wv.z + a.w * wv.w;
        Pack4 h, l;
        split1(a.x, h.b[0], l.b[0]);
        split1(a.y, h.b[1], l.b[1]);
        split1(a.z, h.b[2], l.b[2]);
        split1(a.w, h.b[3], l.b[3]);
        ohp[idx] = h.u;
        olp[idx] = l.u;
    }
    #pragma unroll
    for (int o = 16; o; o >>= 1) s += __shfl_xor_sync(0xffffffffu, s, o);
    if (lane == 0) bout[row] = s;
}

// ---------------- convert: fp32 -> fp16 hi/lo (elementwise, for Wc) ----------
__global__ void conv_hl(const float4* __restrict__ in,
                        __half* __restrict__ oh, __half* __restrict__ ol)
{
    long i = (long)blockIdx.x * 256 + threadIdx.x;
    float4 v = in[i];
    Pack4 h, l;
    split1(v.x, h.b[0], l.b[0]);
    split1(v.y, h.b[1], l.b[1]);
    split1(v.z, h.b[2], l.b[2]);
    split1(v.w, h.b[3], l.b[3]);
    ((uint2*)oh)[i] = h.u;
    ((uint2*)ol)[i] = l.u;
}

// ---------------- mma.sync split-fp16 GEMM, 64x64 warp tiles -----------------
// Block tile 128x128, 128 threads (4 warps, 2M x 2N), warp tile 64x64, BK=32.
// Round-13 pipeline (load -> wait 1 -> sync -> compute -> sync): the trailing
// barrier guarantees buffer (c+1)&1 is free when LOAD_STAGE(c+1) issues.
// TERMS=3: C = Ah@Bh + Ah@Bl + Al@Bh   [logits path]
// TERMS=2: C = Ah@Bh + Ah@Bl           [output path, A = P]
// DUAL=1: gridDim.z = 2*BB; z>=BB selects the second operand set (G5+G6 merged).
// EPI 0: fp32 C.  EPI 1: fp16 hi/lo C.
// EPI 2: fp32 C + biasR + biasC, plus in-register softmax partials:
//        row (max, sumexp) per 64-col chunk -> g_prm/g_prs
//        col (max, sumexp) per 64-row chunk -> g_pcm/g_pcs
#define TILEA   (128 * 80)   // A plane: 128 rows x 32 fp16, pad to 40 -> 10240 B
#define TILEB2  (32 * 256)   // B plane: 32 k-rows x 128 fp16 = 8192 B (swizzled)

template <int EPI, int TERMS, int DUAL>
__global__ void __launch_bounds__(128, 2) gemm_tc(
    const __half* __restrict__ Ah, const __half* __restrict__ Al, long sA, int lda,
    const __half* __restrict__ Bh, const __half* __restrict__ Bl, long sB, int ldb,
    int K,
    float* __restrict__ C, __half* __restrict__ Ch, __half* __restrict__ Cl,
    long sC, int ldc,
    const float* __restrict__ biasR, const float* __restrict__ biasC, int Mtot, int Ntot,
    const __half* __restrict__ Ah2, const __half* __restrict__ Bh2,
    const __half* __restrict__ Bl2, float* __restrict__ C2)
{
    constexpr int NA = (TERMS == 3) ? 2 : 1;
    constexpr int STAGEB = NA * TILEA + 2 * TILEB2;

    extern __shared__ char smem[];
    const uint32_t sbase = smem_to_u32(smem);
    const int tid = threadIdx.x;
    const int lane = tid & 31;
    const int wm = (tid >> 5) >> 1, wn = (tid >> 5) & 1;   // 2x2 warp grid
    const int bm = blockIdx.y * 128, bn = blockIdx.x * 128;

    int zz = blockIdx.z;
    const int sel = DUAL ? (zz >= BB) : 0;
    const int bz  = DUAL ? (zz & (BB - 1)) : zz;

    const __half* AhS = (DUAL && sel) ? Ah2 : Ah;
    const __half* BhS = (DUAL && sel) ? Bh2 : Bh;
    const __half* BlS = (DUAL && sel) ? Bl2 : Bl;
    float*        CS  = (DUAL && sel) ? C2  : C;

    const __half* aP[2] = { AhS + (long)bz * sA,
                            (TERMS == 3) ? (Al + (long)bz * sA) : nullptr };
    const __half* bP[2] = { BhS + (long)bz * sB, BlS + (long)bz * sB };

    float acc[4][8][4];
    #pragma unroll
    for (int i = 0; i < 4; i++)
        #pragma unroll
        for (int j = 0; j < 8; j++)
            #pragma unroll
            for (int q = 0; q < 4; q++) acc[i][j][q] = 0.f;

    const int NC = K >> 5;

    #define LOAD_STAGE(cc, st) do {                                            \
        uint32_t dst0 = sbase + (st) * STAGEB;                                 \
        int k0 = (cc) << 5;                                                    \
        _Pragma("unroll")                                                      \
        for (int p = 0; p < NA; p++)                                           \
            _Pragma("unroll")                                                  \
            for (int h = 0; h < 4; h++) {                                      \
                int slot = tid + h * 128;                                      \
                int row = slot >> 2, seg = slot & 3;                           \
                cp_async16(dst0 + p * TILEA + row * 80 + seg * 16,             \
                           aP[p] + (long)(bm + row) * lda + k0 + seg * 8);     \
            }                                                                  \
        _Pragma("unroll")                                                      \
        for (int p = 0; p < 2; p++)                                            \
            _Pragma("unroll")                                                  \
            for (int h = 0; h < 4; h++) {                                      \
                int slot = tid + h * 128;                                      \
                int row = slot >> 4, seg = slot & 15;                          \
                uint32_t bo = (uint32_t)(row << 8) + (uint32_t)(seg << 4);     \
                bo ^= (uint32_t)(row & 7) << 4;                                \
                cp_async16(dst0 + NA * TILEA + p * TILEB2 + bo,                \
                           bP[p] + (long)(k0 + row) * ldb + bn + seg * 8);     \
            }                                                                  \
        asm volatile("cp.async.commit_group;");                                \
    } while (0)

    LOAD_STAGE(0, 0);

    const int lr = lane & 15;              // A frag row
    const int lc = (lane >> 4) << 3;       // A frag k-col
    const int g8  = lane >> 3;
    const int rowp = ((g8 & 1) << 3) + (lane & 7);   // 0..15 (k within 16)
    const int cs8  = (g8 >> 1) << 3;                 // 0 or 8 (n within 16)

    for (int c = 0; c < NC; c++) {
        if (c + 1 < NC) {
            LOAD_STAGE(c + 1, (c + 1) & 1);
            asm volatile("cp.async.wait_group 1;");
        } else {
            asm volatile("cp.async.wait_group 0;");
        }
        __syncthreads();

        uint32_t sAh = sbase + (c & 1) * STAGEB;
        uint32_t sAl = sAh + TILEA;                  // valid if TERMS==3
        uint32_t sBh = sAh + NA * TILEA;
        uint32_t sBl = sBh + TILEB2;

        #pragma unroll
        for (int kk = 0; kk < 2; kk++) {
            uint32_t fa_h[4][4], fa_l[4][4];
            #pragma unroll
            for (int mm = 0; mm < 4; mm++) {
                uint32_t off = (uint32_t)(wm * 64 + mm * 16 + lr) * 80
                             + (uint32_t)(kk * 16 + lc) * 2;
                ldsm_x4(fa_h[mm], sAh + off);
                if (TERMS == 3) ldsm_x4(fa_l[mm], sAl + off);
            }
            uint32_t fb_h[4][4], fb_l[4][4];
            #pragma unroll
            for (int nn = 0; nn < 4; nn++) {
                uint32_t koff = (uint32_t)(kk * 16 + rowp);
                uint32_t bo = (koff << 8) + (uint32_t)(wn * 64 + nn * 16 + cs8) * 2;
                bo ^= (koff & 7) << 4;
                ldsm_x4_t(fb_h[nn], sBh + bo);
                ldsm_x4_t(fb_l[nn], sBl + bo);
            }
            // term-major issue
            #pragma unroll
            for (int mm = 0; mm < 4; mm++) {
                #pragma unroll
                for (int nt = 0; nt < 8; nt++) {
                    const int nn = nt >> 1, n2 = nt & 1;
                    uint32_t bh2[2] = { fb_h[nn][2 * n2], fb_h[nn][2 * n2 + 1] };
                    mma16816(acc[mm][nt], fa_h[mm], bh2);
                }
            }
            #pragma unroll
            for (int mm = 0; mm < 4; mm++) {
                #pragma unroll
                for (int nt = 0; nt < 8; nt++) {
                    const int nn = nt >> 1, n2 = nt & 1;
                    uint32_t bl2[2] = { fb_l[nn][2 * n2], fb_l[nn][2 * n2 + 1] };
                    mma16816(acc[mm][nt], fa_h[mm], bl2);
                }
            }
            if (TERMS == 3) {
                #pragma unroll
                for (int mm = 0; mm < 4; mm++) {
                    #pragma unroll
                    for (int nt = 0; nt < 8; nt++) {
                        const int nn = nt >> 1, n2 = nt & 1;
                        uint32_t bh2[2] = { fb_h[nn][2 * n2], fb_h[nn][2 * n2 + 1] };
                        mma16816(acc[mm][nt], fa_l[mm], bh2);
                    }
                }
            }
        }
        __syncthreads();
    }

    // ---- epilogue (warp covers 64 rows x 64 cols)
    const int er0 = bm + wm * 64 + (lane >> 2);
    const int ec0 = bn + wn * 64 + ((lane & 3) << 1);

    if (EPI == 2) {
        // add biases into acc, then store
        #pragma unroll
        for (int mm = 0; mm < 4; mm++) {
            int row = er0 + mm * 16;
            float br0 = biasR[bz * Mtot + row], br8 = biasR[bz * Mtot + row + 8];
            #pragma unroll
            for (int nt = 0; nt < 8; nt++) {
                int col = ec0 + nt * 8;
                float bc0 = biasC[bz * Ntot + col], bc1 = biasC[bz * Ntot + col + 1];
                acc[mm][nt][0] += br0 + bc0; acc[mm][nt][1] += br0 + bc1;
                acc[mm][nt][2] += br8 + bc0; acc[mm][nt][3] += br8 + bc1;
                long o = (long)bz * sC + (long)row * ldc + col;
                *(float2*)(CS + o) = make_float2(acc[mm][nt][0], acc[mm][nt][1]);
                *(float2*)(CS + o + (long)8 * ldc) = make_float2(acc[mm][nt][2], acc[mm][nt][3]);
            }
        }
        // ---- row softmax partials (this warp's 64-col chunk)
        const int cn = blockIdx.x * 2 + wn;   // col-chunk 0..7
        #pragma unroll
        for (int mm = 0; mm < 4; mm++) {
            #pragma unroll
            for (int h = 0; h < 2; h++) {
                float m = -1e30f;
                #pragma unroll
                for (int nt = 0; nt < 8; nt++) {
                    m = fmaxf(m, acc[mm][nt][2 * h]);
                    m = fmaxf(m, acc[mm][nt][2 * h + 1]);
                }
                float s = 0.f;
                #pragma unroll
                for (int nt = 0; nt < 8; nt++)
                    s += __expf(acc[mm][nt][2 * h] - m) + __expf(acc[mm][nt][2 * h + 1] - m);
                #pragma unroll
                for (int o = 1; o <= 2; o <<= 1) {
                    float mo = __shfl_xor_sync(0xffffffffu, m, o);
                    float so = __shfl_xor_sync(0xffffffffu, s, o);
                    float nm = fmaxf(m, mo);
                    s = s * __expf(m - nm) + so * __expf(mo - nm);
                    m = nm;
                }
                if ((lane & 3) == 0) {
                    int row = er0 + mm * 16 + 8 * h;
                    long o = ((long)bz * 8 + cn) * SS + row;
                    g_prm[o] = m; g_prs[o] = s;
                }
            }
        }
        // ---- col softmax partials (this warp's 64-row chunk)
        const int rm = blockIdx.y * 2 + wm;   // row-chunk 0..7
        #pragma unroll
        for (int nt = 0; nt < 8; nt++) {
            #pragma unroll
            for (int p = 0; p < 2; p++) {
                float m = -1e30f;
                #pragma unroll
                for (int mm = 0; mm < 4; mm++) {
                    m = fmaxf(m, acc[mm][nt][p]);
                    m = fmaxf(m, acc[mm][nt][2 + p]);
                }
                float s = 0.f;
                #pragma unroll
                for (int mm = 0; mm < 4; mm++)
                    s += __expf(acc[mm][nt][p] - m) + __expf(acc[mm][nt][2 + p] - m);
                #pragma unroll
                for (int o = 4; o <= 16; o <<= 1) {
                    float mo = __shfl_xor_sync(0xffffffffu, m, o);
                    float so = __shfl_xor_sync(0xffffffffu, s, o);
                    float nm = fmaxf(m, mo);
                    s = s * __expf(m - nm) + so * __expf(mo - nm);
                    m = nm;
                }
                if ((lane >> 2) == 0) {
                    int col = ec0 + nt * 8 + p;
                    long o = ((long)bz * 8 + rm) * SS + col;
                    g_pcm[o] = m; g_pcs[o] = s;
                }
            }
        }
    } else {
        #pragma unroll
        for (int mm = 0; mm < 4; mm++) {
            #pragma unroll
            for (int nt = 0; nt < 8; nt++) {
                int row = er0 + mm * 16;
                int col = ec0 + nt * 8;
                float v0 = acc[mm][nt][0], v1 = acc[mm][nt][1];
                float v2 = acc[mm][nt][2], v3 = acc[mm][nt][3];
                if (EPI == 1) {
                    __half h0, l0, h1, l1;
                    long o = (long)bz * sC + (long)row * ldc + col;
                    split1(v0, h0, l0); split1(v1, h1, l1);
                    *(__half2*)(Ch + o) = __half2(h0, h1);
                    *(__half2*)(Cl + o) = __half2(l0, l1);
                    o += (long)8 * ldc;
                    split1(v2, h0, l0); split1(v3, h1, l1);
                    *(__half2*)(Ch + o) = __half2(h0, h1);
                    *(__half2*)(Cl + o) = __half2(l0, l1);
                } else {
                    long o = (long)bz * sC + (long)row * ldc + col;
                    *(float2*)(CS + o) = make_float2(v0, v1);
                    *(float2*)(CS + o + (long)8 * ldc) = make_float2(v2, v3);
                }
            }
        }
    }
}

// ---------------- probabilities: P1 (fp16) and P2^T (fp16) -------------------
// Row AND col stats combined inline from the 8 per-chunk partials.
__global__ void prob_kernel()
{
    __shared__ float p2t[64 * 65];
    __shared__ float scm[64], scr[64], srm[64], srr[64];
    int b = blockIdx.z;
    int bs0 = blockIdx.y * 64, bt0 = blockIdx.x * 64;
    const float* A = g_A + (long)b * SS * SS;
    int tid = threadIdx.x;

    if (tid < 64) {
        int t = bt0 + tid;
        float M = -1e30f;
        #pragma unroll
        for (int c = 0; c < 8; c++) M = fmaxf(M, g_pcm[((long)b * 8 + c) * SS + t]);
        float S = 0.f;
        #pragma unroll
        for (int c = 0; c < 8; c++)
            S += g_pcs[((long)b * 8 + c) * SS + t] * __expf(g_pcm[((long)b * 8 + c) * SS + t] - M);
        scm[tid] = M;
        scr[tid] = 1.0f / S;
    } else if (tid < 128) {
        int s = bs0 + (tid - 64);
        float M = -1e30f;
        #pragma unroll
        for (int c = 0; c < 8; c++) M = fmaxf(M, g_prm[((long)b * 8 + c) * SS + s]);
        float S = 0.f;
        #pragma unroll
        for (int c = 0; c < 8; c++)
            S += g_prs[((long)b * 8 + c) * SS + s] * __expf(g_prm[((long)b * 8 + c) * SS + s] - M);
        srm[tid - 64] = M;
        srr[tid - 64] = 1.0f / S;
    }
    __syncthreads();

    #pragma unroll
    for (int it = 0; it < 4; it++) {
        int idx = tid + it * 256;
        int r = idx >> 4, c4 = idx & 15;
        int s = bs0 + r;
        float4 v = *(const float4*)(A + (long)s * SS + bt0 + c4 * 4);
        float rm = srm[r];
        float rr = srr[r];
        const float4 cm = *(const float4*)(scm + c4 * 4);
        const float4 cr = *(const float4*)(scr + c4 * 4);
        Pack4 h;
        h.b[0] = __float2half_rn(__expf(v.x - cm.x) * cr.x);
        h.b[1] = __float2half_rn(__expf(v.y - cm.y) * cr.y);
        h.b[2] = __float2half_rn(__expf(v.z - cm.z) * cr.z);
        h.b[3] = __float2half_rn(__expf(v.w - cm.w) * cr.w);
        long o1 = (long)b * SS * SS + (long)s * SS + bt0 + c4 * 4;
        *(uint2*)(g_P1 + o1) = h.u;
        float p2v[4] = { __expf(v.x - rm) * rr, __expf(v.y - rm) * rr,
                         __expf(v.z - rm) * rr, __expf(v.w - rm) * rr };
        #pragma unroll
        for (int q = 0; q < 4; q++) p2t[(c4 * 4 + q) * 65 + r] = p2v[q];
    }
    __syncthreads();
    int c = tid >> 2, g = tid & 3;
    #pragma unroll
    for (int j = 0; j < 4; j++) {
        int rr0 = g * 16 + j * 4;
        Pack4 h;
        #pragma unroll
        for (int q = 0; q < 4; q++) h.b[q] = __float2half_rn(p2t[c * 65 + rr0 + q]);
        long o = (long)b * SS * SS + (long)(bt0 + c) * SS + bs0 + rr0;
        *(uint2*)(g_P2T + o) = h.u;
    }
}

// ---------------- launch -----------------------------------------------------
extern "C" void kernel_launch(void* const* d_in, const int* in_sizes, int n_in,
                              void* d_out, int out_size)
{
    const float* x1 = (const float*)d_in[0];
    const float* x2 = (const float*)d_in[1];
    const float* Wc = (const float*)d_in[2];
    const float* W1 = (const float*)d_in[3];
    const float* W2 = (const float*)d_in[4];
    float* out1 = (float*)d_out;
    float* out2 = out1 + N_SD;

    __half *x1h, *x1l, *x2h, *x2l, *Wch, *Wcl, *x1wh, *x1wl, *P1, *P2T;
    float *pA, *pb1, *pb2;
    cudaGetSymbolAddress((void**)&x1h,  g_x1h);
    cudaGetSymbolAddress((void**)&x1l,  g_x1l);
    cudaGetSymbolAddress((void**)&x2h,  g_x2h);
    cudaGetSymbolAddress((void**)&x2l,  g_x2l);
    cudaGetSymbolAddress((void**)&Wch,  g_Wch);
    cudaGetSymbolAddress((void**)&Wcl,  g_Wcl);
    cudaGetSymbolAddress((void**)&x1wh, g_x1wh);
    cudaGetSymbolAddress((void**)&x1wl, g_x1wl);
    cudaGetSymbolAddress((void**)&P1,   g_P1);
    cudaGetSymbolAddress((void**)&P2T,  g_P2T);
    cudaGetSymbolAddress((void**)&pA,   g_A);
    cudaGetSymbolAddress((void**)&pb1,  g_bias1);
    cudaGetSymbolAddress((void**)&pb2,  g_bias2);

    const int SMEM_T3 = 2 * (2 * TILEA + 2 * TILEB2);   // 73728
    const int SMEM_T2 = 2 * (1 * TILEA + 2 * TILEB2);   // 53248
    cudaFuncSetAttribute(gemm_tc<1, 3, 0>, cudaFuncAttributeMaxDynamicSharedMemorySize, SMEM_T3);
    cudaFuncSetAttribute(gemm_tc<2, 3, 0>, cudaFuncAttributeMaxDynamicSharedMemorySize, SMEM_T3);
    cudaFuncSetAttribute(gemm_tc<0, 2, 1>, cudaFuncAttributeMaxDynamicSharedMemorySize, SMEM_T2);

    const long sSD = (long)SS * DD;
    const long sSq = (long)SS * SS;

    // fused hi/lo converts + bias dots (one read of x1, x2)
    conv_bias<<<(2 * BB * SS) / 8, 256>>>(x1, x2, W1, W2);
    conv_hl<<<(DD * DD / 4) / 256, 256>>>((const float4*)Wc, Wch, Wcl);

    // G1: x1w = x1 @ Wc  (M=512,N=768,K=768); B = Wc natural [d][e]
    gemm_tc<1, 3, 0><<<dim3(DD / 128, SS / 128, BB), 128, SMEM_T3>>>(
        x1h, x1l, sSD, DD, Wch, Wcl, 0, DD, DD,
        nullptr, x1wh, x1wl, sSD, DD, nullptr, nullptr, SS, DD,
        nullptr, nullptr, nullptr, nullptr);

    // G3: A = x1w @ x2r + biases (M=512,N=512,K=768); softmax partials in epilogue
    gemm_tc<2, 3, 0><<<dim3(SS / 128, SS / 128, BB), 128, SMEM_T3>>>(
        x1wh, x1wl, sSD, DD, x2h, x2l, sSD, SS, DD,
        pA, nullptr, nullptr, sSq, SS, pb1, pb2, SS, SS,
        nullptr, nullptr, nullptr, nullptr);

    // probabilities (row+col partials combined inline; no separate stats pass)
    prob_kernel<<<dim3(SS / 64, SS / 64, BB), 256>>>();

    // G5+G6 merged: z<32 -> f_x1 = P1 @ x2 ; z>=32 -> f_x2 = P2^T @ x1
    gemm_tc<0, 2, 1><<<dim3(DD / 128, SS / 128, 2 * BB), 128, SMEM_T2>>>(
        P1, nullptr, sSq, SS, x2h, x2l, sSD, DD, SS,
        out1, nullptr, nullptr, sSD, DD, nullptr, nullptr, SS, DD,
        P2T, x1h, x1l, out2);
}